// round 12
// baseline (speedup 1.0000x reference)
#include <cuda_runtime.h>
#include <cuda_bf16.h>
#include <math.h>
#include <float.h>
#include <stdint.h>

// ---------------- problem constants ----------------
#define BATCH   4
#define NPROP   2048
#define NROWS   (BATCH * NPROP)      // 8192
#define F_IN    12544
#define HID     1024
#define NCLS    91
#define NCLSP   128                  // padded class dim for GEMM3 tile
#define REGC    (4 * NCLS)           // 364
#define DETS    100
#define SCORE_THRESH 0.05f
#define NMS_THRESH   0.5f
#define MIN_SIZE     0.01f
#define IMG_DIM      800.0f
#define BBOX_CLIP    4.135166556742356f   // log(1000/16)
#define CLS_OFFSET   801.0f               // max(H,W)+1
#define MAXC (NPROP * (NCLS - 1))

#define SCALE_A   128.0f
#define SCALE_W   2048.0f
#define DEQ       (1.0f / 262144.0f)      // 2^-18, exact

// ---------------- scratch (device globals) ----------------
__device__ int8_t        g_a8 [(size_t)NROWS * F_IN];   // box_features s8 (x128)
__device__ int8_t        g_w6t8[(size_t)HID * F_IN];    // fc6_w^T s8 (x2048)
__device__ __nv_bfloat16 g_w7t[(size_t)HID * HID];      // fc7_w^T bf16
__device__ __nv_bfloat16 g_wct[(size_t)NCLSP * HID];    // cls_w^T bf16 padded
__device__ __nv_bfloat16 g_h1b[(size_t)NROWS * HID];    // h1 bf16
__device__ float         g_h2 [(size_t)NROWS * HID];    // h2 fp32 (bbox on-demand path)
__device__ __nv_bfloat16 g_h2b[(size_t)NROWS * HID];    // h2 bf16 (logits GEMM input)
__device__ float         g_logits[(size_t)NROWS * NCLS];

__device__ float g_cbox [BATCH][MAXC][4];
__device__ float g_cob  [BATCH][MAXC][4];
__device__ float g_carea[BATCH][MAXC];
__device__ float g_cscore[BATCH][MAXC];
__device__ int   g_clabel[BATCH][MAXC];
__device__ int   g_count[BATCH];

// ---------------- helpers ----------------
__device__ __forceinline__ uint32_t smem_u32(const void* p) {
    uint32_t a;
    asm("{ .reg .u64 t; cvta.to.shared.u64 t, %1; cvt.u32.u64 %0, t; }" : "=r"(a) : "l"(p));
    return a;
}
__device__ __forceinline__ void cp16(uint32_t sdst, const void* gsrc) {
    asm volatile("cp.async.cg.shared.global [%0], [%1], 16;" :: "r"(sdst), "l"(gsrc) : "memory");
}
#define CP_COMMIT() asm volatile("cp.async.commit_group;" ::: "memory")
#define CP_WAIT2()  asm volatile("cp.async.wait_group 2;" ::: "memory")

__device__ __forceinline__ void mma16816(float* d, uint32_t a0, uint32_t a1, uint32_t a2, uint32_t a3,
                                         uint32_t b0, uint32_t b1) {
    asm volatile("mma.sync.aligned.m16n8k16.row.col.f32.bf16.bf16.f32 "
        "{%0,%1,%2,%3}, {%4,%5,%6,%7}, {%8,%9}, {%0,%1,%2,%3};"
        : "+f"(d[0]), "+f"(d[1]), "+f"(d[2]), "+f"(d[3])
        : "r"(a0), "r"(a1), "r"(a2), "r"(a3), "r"(b0), "r"(b1));
}
__device__ __forceinline__ void mma16832_s8(int* d, uint32_t a0, uint32_t a1, uint32_t a2, uint32_t a3,
                                            uint32_t b0, uint32_t b1) {
    asm volatile("mma.sync.aligned.m16n8k32.row.col.s32.s8.s8.s32 "
        "{%0,%1,%2,%3}, {%4,%5,%6,%7}, {%8,%9}, {%0,%1,%2,%3};"
        : "+r"(d[0]), "+r"(d[1]), "+r"(d[2]), "+r"(d[3])
        : "r"(a0), "r"(a1), "r"(a2), "r"(a3), "r"(b0), "r"(b1));
}
#define LDSM4(r0, r1, r2, r3, addr) \
    asm volatile("ldmatrix.sync.aligned.m8n8.x4.shared.b16 {%0,%1,%2,%3}, [%4];" \
        : "=r"(r0), "=r"(r1), "=r"(r2), "=r"(r3) : "r"(addr))

__device__ __forceinline__ int q8(float v, float s) {
    return __float2int_rn(fminf(fmaxf(v * s, -127.0f), 127.0f));
}

// ---------------- init ----------------
__global__ void init_kernel(float* out, int out_size) {
    int i = blockIdx.x * blockDim.x + threadIdx.x;
    if (i < out_size) out[i] = 0.0f;
    if (i < BATCH) g_count[i] = 0;
}

// ---------------- fp32 -> s8 (x128) elementwise ----------------
__global__ void convert_a_s8_kernel(const float* __restrict__ in, int8_t* __restrict__ out, size_t n4) {
    size_t i = (size_t)blockIdx.x * blockDim.x + threadIdx.x;
    if (i >= n4) return;
    float4 v = ((const float4*)in)[i];
    uint32_t p = (uint32_t)(q8(v.x, SCALE_A) & 0xFF)
               | ((uint32_t)(q8(v.y, SCALE_A) & 0xFF) << 8)
               | ((uint32_t)(q8(v.z, SCALE_A) & 0xFF) << 16)
               | ((uint32_t)(q8(v.w, SCALE_A) & 0xFF) << 24);
    ((uint32_t*)out)[i] = p;
}

// ---------------- transpose + convert: [K,N] f32 -> [Npad,K] s8 (x2048) ----------------
__global__ void transpose_conv_s8_kernel(const float* __restrict__ in, int8_t* __restrict__ out,
                                         int K, int N, int Npad) {
    __shared__ float t[32][33];
    int n0 = blockIdx.x * 32, k0 = blockIdx.y * 32;
    int tx = threadIdx.x, ty = threadIdx.y;
    #pragma unroll
    for (int r = ty; r < 32; r += 8) {
        int k = k0 + r, n = n0 + tx;
        t[r][tx] = (k < K && n < N) ? in[(size_t)k * N + n] : 0.0f;
    }
    __syncthreads();
    #pragma unroll
    for (int r = ty; r < 32; r += 8) {
        int n = n0 + r, k = k0 + tx;
        if (n < Npad && k < K) out[(size_t)n * K + k] = (int8_t)q8(t[tx][r], SCALE_W);
    }
}

// ---------------- transpose + convert: [K,N] f32 -> [Npad,K] bf16 ----------------
__global__ void transpose_conv_kernel(const float* __restrict__ in, __nv_bfloat16* __restrict__ out,
                                      int K, int N, int Npad) {
    __shared__ float t[32][33];
    int n0 = blockIdx.x * 32, k0 = blockIdx.y * 32;
    int tx = threadIdx.x, ty = threadIdx.y;
    #pragma unroll
    for (int r = ty; r < 32; r += 8) {
        int k = k0 + r, n = n0 + tx;
        t[r][tx] = (k < K && n < N) ? in[(size_t)k * N + n] : 0.0f;
    }
    __syncthreads();
    #pragma unroll
    for (int r = ty; r < 32; r += 8) {
        int n = n0 + r, k = k0 + tx;
        if (n < Npad && k < K) out[(size_t)n * K + k] = __float2bfloat16(t[tx][r]);
    }
}

// ---------------- IMMA s8 GEMM (GEMM1): h1 = relu(acc*2^-18 + bias) -> bf16 ----------------
// A [M,Ktot] s8, Bt [N,Ktot] s8; block 256, tile 128x128, warp 64x32, K-chunk 64, 4-stage.
#define SPAD8 80                       // bytes per smem row (64 data + 16 pad)
#define ASTG8 (128 * SPAD8)            // 10240 B
#define STG8  (2 * ASTG8)              // 20480 B per stage
#define NST8  4
__global__ __launch_bounds__(256)
void gemm_s8(const int8_t* __restrict__ A, const int8_t* __restrict__ Bt,
             const float* __restrict__ bias, __nv_bfloat16* __restrict__ Cb,
             int Ktot, int Ntot)
{
    extern __shared__ char smem[];
    const uint32_t sb = smem_u32(smem);
    const int tid = threadIdx.x, wid = tid >> 5, lane = tid & 31;
    const int g = lane >> 2, t4 = lane & 3;
    const int m0 = blockIdx.y * 128, n0 = blockIdx.x * 128;
    const int NCH = Ktot >> 6;          // K chunks of 64
    const int mw = (wid & 1) * 64;
    const int nw = (wid >> 1) * 32;

    int acc[4][4][4];
    #pragma unroll
    for (int i = 0; i < 4; i++)
        #pragma unroll
        for (int j = 0; j < 4; j++)
            #pragma unroll
            for (int r = 0; r < 4; r++) acc[i][j][r] = 0;

    const int lrow = tid >> 1;
    const int lpart = tid & 1;

    auto load_chunk = [&](int c, int s) {
        const char* ag = (const char*)(A + (size_t)(m0 + lrow) * Ktot + (c << 6) + lpart * 32);
        uint32_t ad = sb + s * STG8 + lrow * SPAD8 + lpart * 32;
        cp16(ad, ag); cp16(ad + 16, ag + 16);
        const char* bg = (const char*)(Bt + (size_t)(n0 + lrow) * Ktot + (c << 6) + lpart * 32);
        uint32_t bd = ad + ASTG8;
        cp16(bd, bg); cp16(bd + 16, bg + 16);
    };

    #pragma unroll
    for (int c = 0; c < NST8 - 1; c++) { load_chunk(c, c); CP_COMMIT(); }

    for (int c = 0; c < NCH; c++) {
        int s = c & (NST8 - 1);
        CP_WAIT2();
        __syncthreads();
        if (c + NST8 - 1 < NCH) load_chunk(c + NST8 - 1, (c + NST8 - 1) & (NST8 - 1));
        CP_COMMIT();

        const char* as = smem + s * STG8;
        const char* bs = smem + s * STG8 + ASTG8;
        #pragma unroll
        for (int kk = 0; kk < 64; kk += 32) {
            uint32_t af[4][4], bf[4][2];
            #pragma unroll
            for (int i = 0; i < 4; i++) {
                const char* base = as + (mw + i * 16 + g) * SPAD8 + kk + 4 * t4;
                af[i][0] = *(const uint32_t*)(base);
                af[i][1] = *(const uint32_t*)(base + 8 * SPAD8);
                af[i][2] = *(const uint32_t*)(base + 16);
                af[i][3] = *(const uint32_t*)(base + 8 * SPAD8 + 16);
            }
            #pragma unroll
            for (int j = 0; j < 4; j++) {
                const char* base = bs + (nw + j * 8 + g) * SPAD8 + kk + 4 * t4;
                bf[j][0] = *(const uint32_t*)(base);
                bf[j][1] = *(const uint32_t*)(base + 16);
            }
            #pragma unroll
            for (int i = 0; i < 4; i++)
                #pragma unroll
                for (int j = 0; j < 4; j++)
                    mma16832_s8(acc[i][j], af[i][0], af[i][1], af[i][2], af[i][3], bf[j][0], bf[j][1]);
        }
        __syncthreads();
    }

    #pragma unroll
    for (int i = 0; i < 4; i++) {
        #pragma unroll
        for (int j = 0; j < 4; j++) {
            int col = n0 + nw + j * 8 + 2 * t4;
            float b0 = bias[col], b1 = bias[col + 1];
            #pragma unroll
            for (int h = 0; h < 2; h++) {
                int row = m0 + mw + i * 16 + g + h * 8;
                float v0 = fmaxf(__int2float_rn(acc[i][j][2 * h])     * DEQ + b0, 0.0f);
                float v1 = fmaxf(__int2float_rn(acc[i][j][2 * h + 1]) * DEQ + b1, 0.0f);
                __nv_bfloat162 p; p.x = __float2bfloat16(v0); p.y = __float2bfloat16(v1);
                *(__nv_bfloat162*)(Cb + (size_t)row * Ntot + col) = p;
            }
        }
    }
}

// ---------------- HMMA bf16 GEMM (GEMM2/3): 128x128, 64x32 warp, ldmatrix, 4-stage ----------------
#define ROWB 80
#define AST  (128 * ROWB)
#define STG  (2 * AST)
#define NSTAGE 4
template<int OM, bool RELU>            // OM: 1 = fp32 guarded, 2 = fp32 + bf16
__global__ __launch_bounds__(256)
void gemm_hmma(const __nv_bfloat16* __restrict__ A, const __nv_bfloat16* __restrict__ Bt,
               const float* __restrict__ bias, float* __restrict__ C,
               __nv_bfloat16* __restrict__ Cb, int Ktot, int Ntot, int Nvalid)
{
    extern __shared__ char smem[];
    const uint32_t sb = smem_u32(smem);
    const int tid = threadIdx.x, wid = tid >> 5, lane = tid & 31;
    const int g = lane >> 2, t4 = lane & 3;
    const int m0 = blockIdx.y * 128, n0 = blockIdx.x * 128;
    const int NCH = Ktot >> 5;
    const int mw = (wid & 1) * 64;
    const int nw = (wid >> 1) * 32;

    float acc[4][4][4];
    #pragma unroll
    for (int i = 0; i < 4; i++)
        #pragma unroll
        for (int j = 0; j < 4; j++)
            #pragma unroll
            for (int r = 0; r < 4; r++) acc[i][j][r] = 0.0f;

    const uint32_t a_off = (uint32_t)(mw + (lane & 15)) * ROWB + ((lane >> 4) * 8) * 2;
    const uint32_t b_off = (uint32_t)(nw + (lane & 15)) * ROWB + ((lane >> 4) * 8) * 2;

    const int lrow = tid >> 1;
    const int lpart = tid & 1;

    auto load_chunk = [&](int c, int s) {
        const char* ag = (const char*)(A + (size_t)(m0 + lrow) * Ktot + (c << 5) + lpart * 16);
        uint32_t ad = sb + s * STG + lrow * ROWB + lpart * 32;
        cp16(ad, ag); cp16(ad + 16, ag + 16);
        const char* bg = (const char*)(Bt + (size_t)(n0 + lrow) * Ktot + (c << 5) + lpart * 16);
        uint32_t bd = ad + AST;
        cp16(bd, bg); cp16(bd + 16, bg + 16);
    };

    #pragma unroll
    for (int c = 0; c < NSTAGE - 1; c++) { load_chunk(c, c); CP_COMMIT(); }

    for (int c = 0; c < NCH; c++) {
        int s = c & (NSTAGE - 1);
        CP_WAIT2();
        __syncthreads();
        if (c + NSTAGE - 1 < NCH) load_chunk(c + NSTAGE - 1, (c + NSTAGE - 1) & (NSTAGE - 1));
        CP_COMMIT();

        const uint32_t sa = sb + s * STG;
        const uint32_t sbB = sa + AST;
        #pragma unroll
        for (int kk = 0; kk < 32; kk += 16) {
            uint32_t af[4][4], bf[4][2];
            #pragma unroll
            for (int i = 0; i < 4; i++)
                LDSM4(af[i][0], af[i][1], af[i][2], af[i][3],
                      sa + a_off + (uint32_t)(i * 16 * ROWB) + kk * 2);
            #pragma unroll
            for (int jp = 0; jp < 2; jp++)
                LDSM4(bf[2 * jp][0], bf[2 * jp + 1][0], bf[2 * jp][1], bf[2 * jp + 1][1],
                      sbB + b_off + (uint32_t)(jp * 16 * ROWB) + kk * 2);
            #pragma unroll
            for (int i = 0; i < 4; i++)
                #pragma unroll
                for (int j = 0; j < 4; j++)
                    mma16816(acc[i][j], af[i][0], af[i][1], af[i][2], af[i][3], bf[j][0], bf[j][1]);
        }
        __syncthreads();
    }

    #pragma unroll
    for (int i = 0; i < 4; i++) {
        #pragma unroll
        for (int j = 0; j < 4; j++) {
            int col = n0 + nw + j * 8 + 2 * t4;
            float b0, b1;
            if (OM == 1) { b0 = (col < Nvalid) ? bias[col] : 0.0f;
                           b1 = (col + 1 < Nvalid) ? bias[col + 1] : 0.0f; }
            else         { b0 = bias[col]; b1 = bias[col + 1]; }
            #pragma unroll
            for (int h = 0; h < 2; h++) {
                int row = m0 + mw + i * 16 + g + h * 8;
                float v0 = acc[i][j][2 * h]     + b0;
                float v1 = acc[i][j][2 * h + 1] + b1;
                if (RELU) { v0 = fmaxf(v0, 0.0f); v1 = fmaxf(v1, 0.0f); }
                if (OM == 2) {
                    __nv_bfloat162 p; p.x = __float2bfloat16(v0); p.y = __float2bfloat16(v1);
                    *(__nv_bfloat162*)(Cb + (size_t)row * Ntot + col) = p;
                    *(float2*)(C + (size_t)row * Ntot + col) = make_float2(v0, v1);
                }
                if (OM == 1) {
                    if (col < Nvalid)     C[(size_t)row * Nvalid + col]     = v0;
                    if (col + 1 < Nvalid) C[(size_t)row * Nvalid + col + 1] = v1;
                }
            }
        }
    }
}

// ---------------- softmax + threshold + on-demand bbox decode ----------------
__global__ void softmax_cand_kernel(const float* __restrict__ bbox_w,
                                    const float* __restrict__ bbox_b,
                                    const float* __restrict__ proposals)
{
    int warp = (blockIdx.x * blockDim.x + threadIdx.x) >> 5;
    int lane = threadIdx.x & 31;
    if (warp >= NROWS) return;
    int n = warp;
    int img = n >> 11;

    const float* lrow = g_logits + (size_t)n * NCLS;
    float l0 = (lane      < NCLS) ? lrow[lane]      : -INFINITY;
    float l1 = (lane + 32 < NCLS) ? lrow[lane + 32] : -INFINITY;
    float l2 = (lane + 64 < NCLS) ? lrow[lane + 64] : -INFINITY;

    float mx = fmaxf(l0, fmaxf(l1, l2));
    #pragma unroll
    for (int o = 16; o; o >>= 1) mx = fmaxf(mx, __shfl_xor_sync(0xffffffffu, mx, o));

    float e0 = (lane      < NCLS) ? __expf(l0 - mx) : 0.0f;
    float e1 = (lane + 32 < NCLS) ? __expf(l1 - mx) : 0.0f;
    float e2 = (lane + 64 < NCLS) ? __expf(l2 - mx) : 0.0f;
    float s = e0 + e1 + e2;
    #pragma unroll
    for (int o = 16; o; o >>= 1) s += __shfl_xor_sync(0xffffffffu, s, o);
    float inv = 1.0f / s;

    #pragma unroll
    for (int base = 0; base < 96; base += 32) {
        int c = base + lane;
        float sc = (base == 0 ? e0 : (base == 32 ? e1 : e2)) * inv;
        bool cand = (c >= 1 && c < NCLS && sc > SCORE_THRESH);
        unsigned mask = __ballot_sync(0xffffffffu, cand);
        while (mask) {
            int src = __ffs(mask) - 1;
            mask &= mask - 1;
            int   cs  = base + src;
            float scs = __shfl_sync(0xffffffffu, sc, src);

            float rel[4];
            #pragma unroll
            for (int j = 0; j < 4; j++) {
                float acc = 0.0f;
                const float* h2row = g_h2 + (size_t)n * HID;
                for (int k = lane; k < HID; k += 32)
                    acc = fmaf(h2row[k], bbox_w[(size_t)k * REGC + 4 * cs + j], acc);
                #pragma unroll
                for (int o = 16; o; o >>= 1) acc += __shfl_xor_sync(0xffffffffu, acc, o);
                rel[j] = acc + bbox_b[4 * cs + j];
            }

            if (lane == 0) {
                float px1 = proposals[(size_t)n * 4 + 0];
                float py1 = proposals[(size_t)n * 4 + 1];
                float px2 = proposals[(size_t)n * 4 + 2];
                float py2 = proposals[(size_t)n * 4 + 3];
                float w  = px2 - px1, h = py2 - py1;
                float cx = px1 + 0.5f * w, cy = py1 + 0.5f * h;
                float dx = rel[0] * 0.1f, dy = rel[1] * 0.1f;
                float dw = fminf(rel[2] * 0.2f, BBOX_CLIP);
                float dh = fminf(rel[3] * 0.2f, BBOX_CLIP);
                float pcx = dx * w + cx, pcy = dy * h + cy;
                float pw = expf(dw) * w, ph = expf(dh) * h;
                float x1 = pcx - 0.5f * pw, y1 = pcy - 0.5f * ph;
                float x2 = pcx + 0.5f * pw, y2 = pcy + 0.5f * ph;
                x1 = fminf(fmaxf(x1, 0.0f), IMG_DIM);
                x2 = fminf(fmaxf(x2, 0.0f), IMG_DIM);
                y1 = fminf(fmaxf(y1, 0.0f), IMG_DIM);
                y2 = fminf(fmaxf(y2, 0.0f), IMG_DIM);
                float bw = x2 - x1, bh = y2 - y1;
                if (bw >= MIN_SIZE && bh >= MIN_SIZE) {
                    int idx = atomicAdd(&g_count[img], 1);
                    float off = (float)cs * CLS_OFFSET;
                    g_cbox[img][idx][0] = x1; g_cbox[img][idx][1] = y1;
                    g_cbox[img][idx][2] = x2; g_cbox[img][idx][3] = y2;
                    float ox1 = x1 + off, oy1 = y1 + off, ox2 = x2 + off, oy2 = y2 + off;
                    g_cob[img][idx][0] = ox1; g_cob[img][idx][1] = oy1;
                    g_cob[img][idx][2] = ox2; g_cob[img][idx][3] = oy2;
                    g_carea[img][idx]  = (ox2 - ox1) * (oy2 - oy1);
                    g_cscore[img][idx] = scs;
                    g_clabel[img][idx] = cs;
                }
            }
        }
    }
}

// ---------------- greedy batched NMS ----------------
__global__ void nms_kernel(float* __restrict__ out)
{
    __shared__ float s_val[256];
    __shared__ int   s_idx[256];
    __shared__ float s_bb[4];
    __shared__ float s_barea;

    int img = blockIdx.x;
    int tid = threadIdx.x;
    int cnt = g_count[img];

    for (int d = 0; d < DETS; d++) {
        float bv = -INFINITY;
        int   bi = -1;
        for (int i = tid; i < cnt; i += 256) {
            float v = g_cscore[img][i];
            if (v > bv || (v == bv && i < bi)) { bv = v; bi = i; }
        }
        s_val[tid] = bv; s_idx[tid] = bi;
        __syncthreads();
        for (int o = 128; o; o >>= 1) {
            if (tid < o) {
                float v2 = s_val[tid + o]; int i2 = s_idx[tid + o];
                float v1 = s_val[tid];     int i1 = s_idx[tid];
                if (v2 > v1 || (v2 == v1 && i2 != -1 && (i1 == -1 || i2 < i1))) {
                    s_val[tid] = v2; s_idx[tid] = i2;
                }
            }
            __syncthreads();
        }
        float bestv = s_val[0];
        int   besti = s_idx[0];
        if (besti < 0 || !isfinite(bestv)) break;

        if (tid == 0) {
            out[((size_t)img * DETS + d) * 4 + 0] = g_cbox[img][besti][0];
            out[((size_t)img * DETS + d) * 4 + 1] = g_cbox[img][besti][1];
            out[((size_t)img * DETS + d) * 4 + 2] = g_cbox[img][besti][2];
            out[((size_t)img * DETS + d) * 4 + 3] = g_cbox[img][besti][3];
            out[BATCH * DETS * 4 + img * DETS + d] = bestv;
            ((int*)out)[BATCH * DETS * 5 + img * DETS + d] = g_clabel[img][besti];
            s_bb[0] = g_cob[img][besti][0];
            s_bb[1] = g_cob[img][besti][1];
            s_bb[2] = g_cob[img][besti][2];
            s_bb[3] = g_cob[img][besti][3];
            s_barea = g_carea[img][besti];
        }
        __syncthreads();

        float bx1 = s_bb[0], by1 = s_bb[1], bx2 = s_bb[2], by2 = s_bb[3];
        float barea = s_barea;
        for (int i = tid; i < cnt; i += 256) {
            float x1 = fmaxf(g_cob[img][i][0], bx1);
            float y1 = fmaxf(g_cob[img][i][1], by1);
            float x2 = fminf(g_cob[img][i][2], bx2);
            float y2 = fminf(g_cob[img][i][3], by2);
            float inter = fmaxf(x2 - x1, 0.0f) * fmaxf(y2 - y1, 0.0f);
            float uni = fmaxf(g_carea[img][i] + barea - inter, 1e-6f);
            if (inter / uni > NMS_THRESH) g_cscore[img][i] = -INFINITY;
        }
        __syncthreads();
    }
}

// ---------------- launch ----------------
extern "C" void kernel_launch(void* const* d_in, const int* in_sizes, int n_in,
                              void* d_out, int out_size)
{
    const float* box_features = (const float*)d_in[0];
    const float* proposals    = (const float*)d_in[1];
    const float* fc6_w = (const float*)d_in[2];
    const float* fc6_b = (const float*)d_in[3];
    const float* fc7_w = (const float*)d_in[4];
    const float* fc7_b = (const float*)d_in[5];
    const float* cls_w = (const float*)d_in[6];
    const float* cls_b = (const float*)d_in[7];
    const float* bbox_w = (const float*)d_in[8];
    const float* bbox_b = (const float*)d_in[9];
    float* out = (float*)d_out;

    int8_t *p_a8, *p_w6t8;
    __nv_bfloat16 *p_w7t, *p_wct, *p_h1b, *p_h2b;
    float *p_h2, *p_logits;
    cudaGetSymbolAddress((void**)&p_a8,   g_a8);
    cudaGetSymbolAddress((void**)&p_w6t8, g_w6t8);
    cudaGetSymbolAddress((void**)&p_w7t,  g_w7t);
    cudaGetSymbolAddress((void**)&p_wct,  g_wct);
    cudaGetSymbolAddress((void**)&p_h1b,  g_h1b);
    cudaGetSymbolAddress((void**)&p_h2b,  g_h2b);
    cudaGetSymbolAddress((void**)&p_h2,   g_h2);
    cudaGetSymbolAddress((void**)&p_logits, g_logits);

    const int SMEM  = NSTAGE * STG;    // 81920
    const int SMEM8 = NST8 * STG8;     // 81920
    cudaFuncSetAttribute(gemm_s8,             cudaFuncAttributeMaxDynamicSharedMemorySize, SMEM8);
    cudaFuncSetAttribute(gemm_hmma<2, true>,  cudaFuncAttributeMaxDynamicSharedMemorySize, SMEM);
    cudaFuncSetAttribute(gemm_hmma<1, false>, cudaFuncAttributeMaxDynamicSharedMemorySize, SMEM);

    init_kernel<<<(out_size + 255) / 256, 256>>>(out, out_size);

    // convert box_features fp32 -> s8 (x128)
    size_t n4 = (size_t)NROWS * F_IN / 4;
    convert_a_s8_kernel<<<(unsigned)((n4 + 255) / 256), 256>>>(box_features, p_a8, n4);

    // weights: fc6 -> s8^T (x2048); fc7, cls -> bf16^T
    transpose_conv_s8_kernel<<<dim3((HID + 31) / 32, (F_IN + 31) / 32), dim3(32, 8)>>>(fc6_w, p_w6t8, F_IN, HID, HID);
    transpose_conv_kernel<<<dim3((HID + 31) / 32, (HID + 31) / 32), dim3(32, 8)>>>(fc7_w, p_w7t, HID, HID, HID);
    transpose_conv_kernel<<<dim3((NCLSP + 31) / 32, (HID + 31) / 32), dim3(32, 8)>>>(cls_w, p_wct, HID, NCLS, NCLSP);

    // GEMM1 (s8 IMMA): h1 = relu(A @ W6 + b6) -> bf16
    gemm_s8<<<dim3(HID / 128, NROWS / 128), 256, SMEM8>>>(
        p_a8, p_w6t8, fc6_b, p_h1b, F_IN, HID);

    // GEMM2 (bf16): h2 = relu(h1 @ W7 + b7) -> fp32 + bf16
    gemm_hmma<2, true><<<dim3(HID / 128, NROWS / 128), 256, SMEM>>>(
        p_h1b, p_w7t, fc7_b, p_h2, p_h2b, HID, HID, HID);

    // GEMM3 (bf16): logits = h2 @ Wc + bc -> fp32 [8192, 91]
    gemm_hmma<1, false><<<dim3(1, NROWS / 128), 256, SMEM>>>(
        p_h2b, p_wct, cls_b, p_logits, nullptr, HID, NCLSP, NCLS);

    softmax_cand_kernel<<<NROWS / 8, 256>>>(bbox_w, bbox_b, proposals);
    nms_kernel<<<BATCH, 256>>>(out);
}

// round 13
// speedup vs baseline: 1.1676x; 1.1676x over previous
#include <cuda_runtime.h>
#include <cuda_bf16.h>
#include <math.h>
#include <float.h>
#include <stdint.h>

// ---------------- problem constants ----------------
#define BATCH   4
#define NPROP   2048
#define NROWS   (BATCH * NPROP)      // 8192
#define F_IN    12544
#define HID     1024
#define NCLS    91
#define NCLSP   128                  // padded class dim for GEMM3 tile
#define REGC    (4 * NCLS)           // 364
#define DETS    100
#define SCORE_THRESH 0.05f
#define NMS_THRESH   0.5f
#define MIN_SIZE     0.01f
#define IMG_DIM      800.0f
#define BBOX_CLIP    4.135166556742356f   // log(1000/16)
#define CLS_OFFSET   801.0f               // max(H,W)+1
#define MAXC (NPROP * (NCLS - 1))

// ---------------- scratch (device globals) ----------------
__device__ __nv_bfloat16 g_w6t[(size_t)HID * F_IN];     // fc6_w^T bf16 [1024,12544]
__device__ __nv_bfloat16 g_w7t[(size_t)HID * HID];      // fc7_w^T bf16
__device__ __nv_bfloat16 g_wct[(size_t)NCLSP * HID];    // cls_w^T bf16 padded
__device__ __nv_bfloat16 g_h1b[(size_t)NROWS * HID];    // h1 bf16
__device__ float         g_h2 [(size_t)NROWS * HID];    // h2 fp32 (bbox on-demand path)
__device__ __nv_bfloat16 g_h2b[(size_t)NROWS * HID];    // h2 bf16 (logits GEMM input)
__device__ float         g_logits[(size_t)NROWS * NCLS];

__device__ float g_cbox [BATCH][MAXC][4];
__device__ float g_cob  [BATCH][MAXC][4];
__device__ float g_carea[BATCH][MAXC];
__device__ float g_cscore[BATCH][MAXC];
__device__ int   g_clabel[BATCH][MAXC];
__device__ int   g_count[BATCH];

// ---------------- helpers ----------------
__device__ __forceinline__ uint32_t smem_u32(const void* p) {
    uint32_t a;
    asm("{ .reg .u64 t; cvta.to.shared.u64 t, %1; cvt.u32.u64 %0, t; }" : "=r"(a) : "l"(p));
    return a;
}
__device__ __forceinline__ void cp16(uint32_t sdst, const void* gsrc) {
    asm volatile("cp.async.cg.shared.global [%0], [%1], 16;" :: "r"(sdst), "l"(gsrc) : "memory");
}
#define CP_COMMIT() asm volatile("cp.async.commit_group;" ::: "memory")
#define CP_WAIT0()  asm volatile("cp.async.wait_group 0;" ::: "memory")
#define CP_WAIT1()  asm volatile("cp.async.wait_group 1;" ::: "memory")
#define CP_WAIT2()  asm volatile("cp.async.wait_group 2;" ::: "memory")

__device__ __forceinline__ void mma16816(float* d, uint32_t a0, uint32_t a1, uint32_t a2, uint32_t a3,
                                         uint32_t b0, uint32_t b1) {
    asm volatile("mma.sync.aligned.m16n8k16.row.col.f32.bf16.bf16.f32 "
        "{%0,%1,%2,%3}, {%4,%5,%6,%7}, {%8,%9}, {%0,%1,%2,%3};"
        : "+f"(d[0]), "+f"(d[1]), "+f"(d[2]), "+f"(d[3])
        : "r"(a0), "r"(a1), "r"(a2), "r"(a3), "r"(b0), "r"(b1));
}
#define LDSM4(r0, r1, r2, r3, addr) \
    asm volatile("ldmatrix.sync.aligned.m8n8.x4.shared.b16 {%0,%1,%2,%3}, [%4];" \
        : "=r"(r0), "=r"(r1), "=r"(r2), "=r"(r3) : "r"(addr))

__device__ __forceinline__ uint32_t pack_bf16x2(float lo, float hi) {
    __nv_bfloat162 p = __floats2bfloat162_rn(lo, hi);
    return *(uint32_t*)&p;
}

// ---------------- init ----------------
__global__ void init_kernel(float* out, int out_size) {
    int i = blockIdx.x * blockDim.x + threadIdx.x;
    if (i < out_size) out[i] = 0.0f;
    if (i < BATCH) g_count[i] = 0;
}

// ---------------- transpose + convert: [K,N] f32 -> [Npad,K] bf16 ----------------
__global__ void transpose_conv_kernel(const float* __restrict__ in, __nv_bfloat16* __restrict__ out,
                                      int K, int N, int Npad) {
    __shared__ float t[32][33];
    int n0 = blockIdx.x * 32, k0 = blockIdx.y * 32;
    int tx = threadIdx.x, ty = threadIdx.y;
    #pragma unroll
    for (int r = ty; r < 32; r += 8) {
        int k = k0 + r, n = n0 + tx;
        t[r][tx] = (k < K && n < N) ? in[(size_t)k * N + n] : 0.0f;
    }
    __syncthreads();
    #pragma unroll
    for (int r = ty; r < 32; r += 8) {
        int n = n0 + r, k = k0 + tx;
        if (n < Npad && k < K) out[(size_t)n * K + k] = __float2bfloat16(t[tx][r]);
    }
}

// ---------------- GEMM1 fused: A fp32 -> in-smem bf16 convert -> HMMA ----------------
// A [M,Ktot] fp32 row-major, Bt [N,Ktot] bf16 row-major.
// 128x128 tile, 64x32 warp tile, K-chunk 32, 3-stage (fp32A 16K + bf16A 10K + B 10K each).
#define ROWB  80                       // bf16 smem row bytes (64 data + 16 pad)
#define F_A32 16384                    // fp32 A stage bytes
#define F_AB  (128 * ROWB)             // 10240
#define F_BOF (F_A32 + F_AB)           // B offset in stage
#define STGF  (F_A32 + 2 * F_AB)       // 36864 per stage
__global__ __launch_bounds__(256, 2)
void gemm_f32a(const float* __restrict__ A, const __nv_bfloat16* __restrict__ Bt,
               const float* __restrict__ bias, __nv_bfloat16* __restrict__ Cb,
               int Ktot, int Ntot)
{
    extern __shared__ char smem[];
    const uint32_t sb = smem_u32(smem);
    const int tid = threadIdx.x, wid = tid >> 5, lane = tid & 31;
    const int g = lane >> 2, t4 = lane & 3;
    const int m0 = blockIdx.y * 128, n0 = blockIdx.x * 128;
    const int NCH = Ktot >> 5;          // K chunks of 32
    const int mw = (wid & 1) * 64;
    const int nw = (wid >> 1) * 32;

    float acc[4][4][4];
    #pragma unroll
    for (int i = 0; i < 4; i++)
        #pragma unroll
        for (int j = 0; j < 4; j++)
            #pragma unroll
            for (int r = 0; r < 4; r++) acc[i][j][r] = 0.0f;

    const uint32_t a_off = (uint32_t)(mw + (lane & 15)) * ROWB + ((lane >> 4) * 8) * 2;
    const uint32_t b_off = (uint32_t)(nw + (lane & 15)) * ROWB + ((lane >> 4) * 8) * 2;

    const int lrow = tid >> 1;          // 0..127
    const int lpart = tid & 1;

    auto load_chunk = [&](int c, int s) {
        // A fp32: row lrow, 64B half selected by lpart (row = 128B)
        const char* ag = (const char*)(A + (size_t)(m0 + lrow) * Ktot + (c << 5)) + lpart * 64;
        uint32_t ad = sb + s * STGF + lrow * 128 + lpart * 64;
        cp16(ad, ag); cp16(ad + 16, ag + 16); cp16(ad + 32, ag + 32); cp16(ad + 48, ag + 48);
        // B bf16: row lrow, 32B half
        const char* bg = (const char*)(Bt + (size_t)(n0 + lrow) * Ktot + (c << 5)) + lpart * 32;
        uint32_t bd = sb + s * STGF + F_BOF + lrow * ROWB + lpart * 32;
        cp16(bd, bg); cp16(bd + 16, bg + 16);
    };

    auto convert_chunk = [&](int s) {
        uint32_t src = sb + s * STGF + lrow * 128 + lpart * 64;
        uint32_t dst = sb + s * STGF + F_A32 + lrow * ROWB + lpart * 32;
        float4 f0, f1, f2, f3;
        asm volatile("ld.shared.v4.f32 {%0,%1,%2,%3}, [%4];" : "=f"(f0.x),"=f"(f0.y),"=f"(f0.z),"=f"(f0.w) : "r"(src));
        asm volatile("ld.shared.v4.f32 {%0,%1,%2,%3}, [%4];" : "=f"(f1.x),"=f"(f1.y),"=f"(f1.z),"=f"(f1.w) : "r"(src + 16));
        asm volatile("ld.shared.v4.f32 {%0,%1,%2,%3}, [%4];" : "=f"(f2.x),"=f"(f2.y),"=f"(f2.z),"=f"(f2.w) : "r"(src + 32));
        asm volatile("ld.shared.v4.f32 {%0,%1,%2,%3}, [%4];" : "=f"(f3.x),"=f"(f3.y),"=f"(f3.z),"=f"(f3.w) : "r"(src + 48));
        uint32_t r0 = pack_bf16x2(f0.x, f0.y), r1 = pack_bf16x2(f0.z, f0.w);
        uint32_t r2 = pack_bf16x2(f1.x, f1.y), r3 = pack_bf16x2(f1.z, f1.w);
        uint32_t r4 = pack_bf16x2(f2.x, f2.y), r5 = pack_bf16x2(f2.z, f2.w);
        uint32_t r6 = pack_bf16x2(f3.x, f3.y), r7 = pack_bf16x2(f3.z, f3.w);
        asm volatile("st.shared.v4.b32 [%0], {%1,%2,%3,%4};" :: "r"(dst),      "r"(r0),"r"(r1),"r"(r2),"r"(r3) : "memory");
        asm volatile("st.shared.v4.b32 [%0], {%1,%2,%3,%4};" :: "r"(dst + 16), "r"(r4),"r"(r5),"r"(r6),"r"(r7) : "memory");
    };

    // prologue: chunks 0,1 in flight; convert chunk 0
    load_chunk(0, 0); CP_COMMIT();
    load_chunk(1, 1); CP_COMMIT();
    CP_WAIT1();                 // chunk 0 arrived
    __syncthreads();
    convert_chunk(0);

    for (int c = 0; c < NCH; c++) {
        int s = c % 3;
        CP_WAIT0();             // chunk c+1 (fp32 + B) arrived
        __syncthreads();        // conversion of c visible; MMA(c-1) readers done before reuse
        if (c + 2 < NCH) { load_chunk(c + 2, (c + 2) % 3); }
        CP_COMMIT();
        if (c + 1 < NCH) convert_chunk((c + 1) % 3);

        const uint32_t sa = sb + s * STGF + F_A32;
        const uint32_t sbB = sb + s * STGF + F_BOF;
        #pragma unroll
        for (int kk = 0; kk < 32; kk += 16) {
            uint32_t af[4][4], bf[4][2];
            #pragma unroll
            for (int i = 0; i < 4; i++)
                LDSM4(af[i][0], af[i][1], af[i][2], af[i][3],
                      sa + a_off + (uint32_t)(i * 16 * ROWB) + kk * 2);
            #pragma unroll
            for (int jp = 0; jp < 2; jp++)
                LDSM4(bf[2 * jp][0], bf[2 * jp + 1][0], bf[2 * jp][1], bf[2 * jp + 1][1],
                      sbB + b_off + (uint32_t)(jp * 16 * ROWB) + kk * 2);
            #pragma unroll
            for (int i = 0; i < 4; i++)
                #pragma unroll
                for (int j = 0; j < 4; j++)
                    mma16816(acc[i][j], af[i][0], af[i][1], af[i][2], af[i][3], bf[j][0], bf[j][1]);
        }
    }

    // epilogue: h1 = relu(acc + bias) -> bf16
    #pragma unroll
    for (int i = 0; i < 4; i++) {
        #pragma unroll
        for (int j = 0; j < 4; j++) {
            int col = n0 + nw + j * 8 + 2 * t4;
            float b0 = bias[col], b1 = bias[col + 1];
            #pragma unroll
            for (int h = 0; h < 2; h++) {
                int row = m0 + mw + i * 16 + g + h * 8;
                float v0 = fmaxf(acc[i][j][2 * h]     + b0, 0.0f);
                float v1 = fmaxf(acc[i][j][2 * h + 1] + b1, 0.0f);
                __nv_bfloat162 p; p.x = __float2bfloat16(v0); p.y = __float2bfloat16(v1);
                *(__nv_bfloat162*)(Cb + (size_t)row * Ntot + col) = p;
            }
        }
    }
}

// ---------------- HMMA bf16 GEMM (GEMM2/3): 128x128, 64x32 warp, ldmatrix, 4-stage ----------------
#define AST  (128 * ROWB)
#define STG  (2 * AST)
#define NSTAGE 4
template<int OM, bool RELU>            // OM: 1 = fp32 guarded, 2 = fp32 + bf16
__global__ __launch_bounds__(256)
void gemm_hmma(const __nv_bfloat16* __restrict__ A, const __nv_bfloat16* __restrict__ Bt,
               const float* __restrict__ bias, float* __restrict__ C,
               __nv_bfloat16* __restrict__ Cb, int Ktot, int Ntot, int Nvalid)
{
    extern __shared__ char smem[];
    const uint32_t sb = smem_u32(smem);
    const int tid = threadIdx.x, wid = tid >> 5, lane = tid & 31;
    const int g = lane >> 2, t4 = lane & 3;
    const int m0 = blockIdx.y * 128, n0 = blockIdx.x * 128;
    const int NCH = Ktot >> 5;
    const int mw = (wid & 1) * 64;
    const int nw = (wid >> 1) * 32;

    float acc[4][4][4];
    #pragma unroll
    for (int i = 0; i < 4; i++)
        #pragma unroll
        for (int j = 0; j < 4; j++)
            #pragma unroll
            for (int r = 0; r < 4; r++) acc[i][j][r] = 0.0f;

    const uint32_t a_off = (uint32_t)(mw + (lane & 15)) * ROWB + ((lane >> 4) * 8) * 2;
    const uint32_t b_off = (uint32_t)(nw + (lane & 15)) * ROWB + ((lane >> 4) * 8) * 2;

    const int lrow = tid >> 1;
    const int lpart = tid & 1;

    auto load_chunk = [&](int c, int s) {
        const char* ag = (const char*)(A + (size_t)(m0 + lrow) * Ktot + (c << 5) + lpart * 16);
        uint32_t ad = sb + s * STG + lrow * ROWB + lpart * 32;
        cp16(ad, ag); cp16(ad + 16, ag + 16);
        const char* bg = (const char*)(Bt + (size_t)(n0 + lrow) * Ktot + (c << 5) + lpart * 16);
        uint32_t bd = ad + AST;
        cp16(bd, bg); cp16(bd + 16, bg + 16);
    };

    #pragma unroll
    for (int c = 0; c < NSTAGE - 1; c++) { load_chunk(c, c); CP_COMMIT(); }

    for (int c = 0; c < NCH; c++) {
        int s = c & (NSTAGE - 1);
        CP_WAIT2();
        __syncthreads();
        if (c + NSTAGE - 1 < NCH) load_chunk(c + NSTAGE - 1, (c + NSTAGE - 1) & (NSTAGE - 1));
        CP_COMMIT();

        const uint32_t sa = sb + s * STG;
        const uint32_t sbB = sa + AST;
        #pragma unroll
        for (int kk = 0; kk < 32; kk += 16) {
            uint32_t af[4][4], bf[4][2];
            #pragma unroll
            for (int i = 0; i < 4; i++)
                LDSM4(af[i][0], af[i][1], af[i][2], af[i][3],
                      sa + a_off + (uint32_t)(i * 16 * ROWB) + kk * 2);
            #pragma unroll
            for (int jp = 0; jp < 2; jp++)
                LDSM4(bf[2 * jp][0], bf[2 * jp + 1][0], bf[2 * jp][1], bf[2 * jp + 1][1],
                      sbB + b_off + (uint32_t)(jp * 16 * ROWB) + kk * 2);
            #pragma unroll
            for (int i = 0; i < 4; i++)
                #pragma unroll
                for (int j = 0; j < 4; j++)
                    mma16816(acc[i][j], af[i][0], af[i][1], af[i][2], af[i][3], bf[j][0], bf[j][1]);
        }
        __syncthreads();
    }

    #pragma unroll
    for (int i = 0; i < 4; i++) {
        #pragma unroll
        for (int j = 0; j < 4; j++) {
            int col = n0 + nw + j * 8 + 2 * t4;
            float b0, b1;
            if (OM == 1) { b0 = (col < Nvalid) ? bias[col] : 0.0f;
                           b1 = (col + 1 < Nvalid) ? bias[col + 1] : 0.0f; }
            else         { b0 = bias[col]; b1 = bias[col + 1]; }
            #pragma unroll
            for (int h = 0; h < 2; h++) {
                int row = m0 + mw + i * 16 + g + h * 8;
                float v0 = acc[i][j][2 * h]     + b0;
                float v1 = acc[i][j][2 * h + 1] + b1;
                if (RELU) { v0 = fmaxf(v0, 0.0f); v1 = fmaxf(v1, 0.0f); }
                if (OM == 2) {
                    __nv_bfloat162 p; p.x = __float2bfloat16(v0); p.y = __float2bfloat16(v1);
                    *(__nv_bfloat162*)(Cb + (size_t)row * Ntot + col) = p;
                    *(float2*)(C + (size_t)row * Ntot + col) = make_float2(v0, v1);
                }
                if (OM == 1) {
                    if (col < Nvalid)     C[(size_t)row * Nvalid + col]     = v0;
                    if (col + 1 < Nvalid) C[(size_t)row * Nvalid + col + 1] = v1;
                }
            }
        }
    }
}

// ---------------- softmax + threshold + on-demand bbox decode ----------------
__global__ void softmax_cand_kernel(const float* __restrict__ bbox_w,
                                    const float* __restrict__ bbox_b,
                                    const float* __restrict__ proposals)
{
    int warp = (blockIdx.x * blockDim.x + threadIdx.x) >> 5;
    int lane = threadIdx.x & 31;
    if (warp >= NROWS) return;
    int n = warp;
    int img = n >> 11;

    const float* lrow = g_logits + (size_t)n * NCLS;
    float l0 = (lane      < NCLS) ? lrow[lane]      : -INFINITY;
    float l1 = (lane + 32 < NCLS) ? lrow[lane + 32] : -INFINITY;
    float l2 = (lane + 64 < NCLS) ? lrow[lane + 64] : -INFINITY;

    float mx = fmaxf(l0, fmaxf(l1, l2));
    #pragma unroll
    for (int o = 16; o; o >>= 1) mx = fmaxf(mx, __shfl_xor_sync(0xffffffffu, mx, o));

    float e0 = (lane      < NCLS) ? __expf(l0 - mx) : 0.0f;
    float e1 = (lane + 32 < NCLS) ? __expf(l1 - mx) : 0.0f;
    float e2 = (lane + 64 < NCLS) ? __expf(l2 - mx) : 0.0f;
    float s = e0 + e1 + e2;
    #pragma unroll
    for (int o = 16; o; o >>= 1) s += __shfl_xor_sync(0xffffffffu, s, o);
    float inv = 1.0f / s;

    #pragma unroll
    for (int base = 0; base < 96; base += 32) {
        int c = base + lane;
        float sc = (base == 0 ? e0 : (base == 32 ? e1 : e2)) * inv;
        bool cand = (c >= 1 && c < NCLS && sc > SCORE_THRESH);
        unsigned mask = __ballot_sync(0xffffffffu, cand);
        while (mask) {
            int src = __ffs(mask) - 1;
            mask &= mask - 1;
            int   cs  = base + src;
            float scs = __shfl_sync(0xffffffffu, sc, src);

            float rel[4];
            #pragma unroll
            for (int j = 0; j < 4; j++) {
                float acc = 0.0f;
                const float* h2row = g_h2 + (size_t)n * HID;
                for (int k = lane; k < HID; k += 32)
                    acc = fmaf(h2row[k], bbox_w[(size_t)k * REGC + 4 * cs + j], acc);
                #pragma unroll
                for (int o = 16; o; o >>= 1) acc += __shfl_xor_sync(0xffffffffu, acc, o);
                rel[j] = acc + bbox_b[4 * cs + j];
            }

            if (lane == 0) {
                float px1 = proposals[(size_t)n * 4 + 0];
                float py1 = proposals[(size_t)n * 4 + 1];
                float px2 = proposals[(size_t)n * 4 + 2];
                float py2 = proposals[(size_t)n * 4 + 3];
                float w  = px2 - px1, h = py2 - py1;
                float cx = px1 + 0.5f * w, cy = py1 + 0.5f * h;
                float dx = rel[0] * 0.1f, dy = rel[1] * 0.1f;
                float dw = fminf(rel[2] * 0.2f, BBOX_CLIP);
                float dh = fminf(rel[3] * 0.2f, BBOX_CLIP);
                float pcx = dx * w + cx, pcy = dy * h + cy;
                float pw = expf(dw) * w, ph = expf(dh) * h;
                float x1 = pcx - 0.5f * pw, y1 = pcy - 0.5f * ph;
                float x2 = pcx + 0.5f * pw, y2 = pcy + 0.5f * ph;
                x1 = fminf(fmaxf(x1, 0.0f), IMG_DIM);
                x2 = fminf(fmaxf(x2, 0.0f), IMG_DIM);
                y1 = fminf(fmaxf(y1, 0.0f), IMG_DIM);
                y2 = fminf(fmaxf(y2, 0.0f), IMG_DIM);
                float bw = x2 - x1, bh = y2 - y1;
                if (bw >= MIN_SIZE && bh >= MIN_SIZE) {
                    int idx = atomicAdd(&g_count[img], 1);
                    float off = (float)cs * CLS_OFFSET;
                    g_cbox[img][idx][0] = x1; g_cbox[img][idx][1] = y1;
                    g_cbox[img][idx][2] = x2; g_cbox[img][idx][3] = y2;
                    float ox1 = x1 + off, oy1 = y1 + off, ox2 = x2 + off, oy2 = y2 + off;
                    g_cob[img][idx][0] = ox1; g_cob[img][idx][1] = oy1;
                    g_cob[img][idx][2] = ox2; g_cob[img][idx][3] = oy2;
                    g_carea[img][idx]  = (ox2 - ox1) * (oy2 - oy1);
                    g_cscore[img][idx] = scs;
                    g_clabel[img][idx] = cs;
                }
            }
        }
    }
}

// ---------------- greedy batched NMS ----------------
__global__ void nms_kernel(float* __restrict__ out)
{
    __shared__ float s_val[256];
    __shared__ int   s_idx[256];
    __shared__ float s_bb[4];
    __shared__ float s_barea;

    int img = blockIdx.x;
    int tid = threadIdx.x;
    int cnt = g_count[img];

    for (int d = 0; d < DETS; d++) {
        float bv = -INFINITY;
        int   bi = -1;
        for (int i = tid; i < cnt; i += 256) {
            float v = g_cscore[img][i];
            if (v > bv || (v == bv && i < bi)) { bv = v; bi = i; }
        }
        s_val[tid] = bv; s_idx[tid] = bi;
        __syncthreads();
        for (int o = 128; o; o >>= 1) {
            if (tid < o) {
                float v2 = s_val[tid + o]; int i2 = s_idx[tid + o];
                float v1 = s_val[tid];     int i1 = s_idx[tid];
                if (v2 > v1 || (v2 == v1 && i2 != -1 && (i1 == -1 || i2 < i1))) {
                    s_val[tid] = v2; s_idx[tid] = i2;
                }
            }
            __syncthreads();
        }
        float bestv = s_val[0];
        int   besti = s_idx[0];
        if (besti < 0 || !isfinite(bestv)) break;

        if (tid == 0) {
            out[((size_t)img * DETS + d) * 4 + 0] = g_cbox[img][besti][0];
            out[((size_t)img * DETS + d) * 4 + 1] = g_cbox[img][besti][1];
            out[((size_t)img * DETS + d) * 4 + 2] = g_cbox[img][besti][2];
            out[((size_t)img * DETS + d) * 4 + 3] = g_cbox[img][besti][3];
            out[BATCH * DETS * 4 + img * DETS + d] = bestv;
            ((int*)out)[BATCH * DETS * 5 + img * DETS + d] = g_clabel[img][besti];
            s_bb[0] = g_cob[img][besti][0];
            s_bb[1] = g_cob[img][besti][1];
            s_bb[2] = g_cob[img][besti][2];
            s_bb[3] = g_cob[img][besti][3];
            s_barea = g_carea[img][besti];
        }
        __syncthreads();

        float bx1 = s_bb[0], by1 = s_bb[1], bx2 = s_bb[2], by2 = s_bb[3];
        float barea = s_barea;
        for (int i = tid; i < cnt; i += 256) {
            float x1 = fmaxf(g_cob[img][i][0], bx1);
            float y1 = fmaxf(g_cob[img][i][1], by1);
            float x2 = fminf(g_cob[img][i][2], bx2);
            float y2 = fminf(g_cob[img][i][3], by2);
            float inter = fmaxf(x2 - x1, 0.0f) * fmaxf(y2 - y1, 0.0f);
            float uni = fmaxf(g_carea[img][i] + barea - inter, 1e-6f);
            if (inter / uni > NMS_THRESH) g_cscore[img][i] = -INFINITY;
        }
        __syncthreads();
    }
}

// ---------------- launch ----------------
extern "C" void kernel_launch(void* const* d_in, const int* in_sizes, int n_in,
                              void* d_out, int out_size)
{
    const float* box_features = (const float*)d_in[0];
    const float* proposals    = (const float*)d_in[1];
    const float* fc6_w = (const float*)d_in[2];
    const float* fc6_b = (const float*)d_in[3];
    const float* fc7_w = (const float*)d_in[4];
    const float* fc7_b = (const float*)d_in[5];
    const float* cls_w = (const float*)d_in[6];
    const float* cls_b = (const float*)d_in[7];
    const float* bbox_w = (const float*)d_in[8];
    const float* bbox_b = (const float*)d_in[9];
    float* out = (float*)d_out;

    __nv_bfloat16 *p_w6t, *p_w7t, *p_wct, *p_h1b, *p_h2b;
    float *p_h2, *p_logits;
    cudaGetSymbolAddress((void**)&p_w6t, g_w6t);
    cudaGetSymbolAddress((void**)&p_w7t, g_w7t);
    cudaGetSymbolAddress((void**)&p_wct, g_wct);
    cudaGetSymbolAddress((void**)&p_h1b, g_h1b);
    cudaGetSymbolAddress((void**)&p_h2b, g_h2b);
    cudaGetSymbolAddress((void**)&p_h2,  g_h2);
    cudaGetSymbolAddress((void**)&p_logits, g_logits);

    const int SMEMF = 3 * STGF;        // 110592
    const int SMEM  = NSTAGE * STG;    // 81920
    cudaFuncSetAttribute(gemm_f32a,           cudaFuncAttributeMaxDynamicSharedMemorySize, SMEMF);
    cudaFuncSetAttribute(gemm_hmma<2, true>,  cudaFuncAttributeMaxDynamicSharedMemorySize, SMEM);
    cudaFuncSetAttribute(gemm_hmma<1, false>, cudaFuncAttributeMaxDynamicSharedMemorySize, SMEM);

    init_kernel<<<(out_size + 255) / 256, 256>>>(out, out_size);

    // transpose+convert weights: [K,N] f32 -> [Npad,K] bf16
    transpose_conv_kernel<<<dim3((HID + 31) / 32, (F_IN + 31) / 32), dim3(32, 8)>>>(fc6_w, p_w6t, F_IN, HID, HID);
    transpose_conv_kernel<<<dim3((HID + 31) / 32, (HID + 31) / 32), dim3(32, 8)>>>(fc7_w, p_w7t, HID, HID, HID);
    transpose_conv_kernel<<<dim3((NCLSP + 31) / 32, (HID + 31) / 32), dim3(32, 8)>>>(cls_w, p_wct, HID, NCLS, NCLSP);

    // GEMM1 (fused fp32->bf16 convert + HMMA): h1 = relu(A @ W6 + b6) -> bf16
    gemm_f32a<<<dim3(HID / 128, NROWS / 128), 256, SMEMF>>>(
        box_features, p_w6t, fc6_b, p_h1b, F_IN, HID);

    // GEMM2 (bf16): h2 = relu(h1 @ W7 + b7) -> fp32 + bf16
    gemm_hmma<2, true><<<dim3(HID / 128, NROWS / 128), 256, SMEM>>>(
        p_h1b, p_w7t, fc7_b, p_h2, p_h2b, HID, HID, HID);

    // GEMM3 (bf16): logits = h2 @ Wc + bc -> fp32 [8192, 91]
    gemm_hmma<1, false><<<dim3(1, NROWS / 128), 256, SMEM>>>(
        p_h2b, p_wct, cls_b, p_logits, nullptr, HID, NCLSP, NCLS);

    softmax_cand_kernel<<<NROWS / 8, 256>>>(bbox_w, bbox_b, proposals);
    nms_kernel<<<BATCH, 256>>>(out);
}

// round 17
// speedup vs baseline: 1.7992x; 1.5408x over previous
#include <cuda_runtime.h>
#include <cuda_bf16.h>
#include <math.h>
#include <float.h>
#include <stdint.h>

// ---------------- problem constants ----------------
#define BATCH   4
#define NPROP   2048
#define NROWS   (BATCH * NPROP)      // 8192
#define F_IN    12544
#define HID     1024
#define NCLS    91
#define NCLSP   128                  // padded class dim for GEMM3 tile
#define REGC    (4 * NCLS)           // 364
#define DETS    100
#define SCORE_THRESH 0.05f
#define NMS_THRESH   0.5f
#define MIN_SIZE     0.01f
#define IMG_DIM      800.0f
#define BBOX_CLIP    4.135166556742356f   // log(1000/16)
#define CLS_OFFSET   801.0f               // max(H,W)+1
#define MAXC (NPROP * (NCLS - 1))

// ---------------- scratch (device globals) ----------------
__device__ __nv_bfloat16 g_a1 [(size_t)NROWS * F_IN];   // box_features bf16
__device__ __nv_bfloat16 g_w6t[(size_t)HID * F_IN];     // fc6_w^T bf16 [1024,12544]
__device__ __nv_bfloat16 g_w7t[(size_t)HID * HID];      // fc7_w^T bf16
__device__ __nv_bfloat16 g_wct[(size_t)NCLSP * HID];    // cls_w^T bf16 padded
__device__ __nv_bfloat16 g_h1b[(size_t)NROWS * HID];    // h1 bf16
__device__ float         g_h2 [(size_t)NROWS * HID];    // h2 fp32 (bbox on-demand path)
__device__ __nv_bfloat16 g_h2b[(size_t)NROWS * HID];    // h2 bf16 (logits GEMM input)
__device__ float         g_logits[(size_t)NROWS * NCLS];

__device__ float g_cbox [BATCH][MAXC][4];
__device__ float g_cob  [BATCH][MAXC][4];
__device__ float g_carea[BATCH][MAXC];
__device__ float g_cscore[BATCH][MAXC];
__device__ int   g_clabel[BATCH][MAXC];
__device__ int   g_count[BATCH];

// ---------------- helpers ----------------
__device__ __forceinline__ uint32_t smem_u32(const void* p) {
    uint32_t a;
    asm("{ .reg .u64 t; cvta.to.shared.u64 t, %1; cvt.u32.u64 %0, t; }" : "=r"(a) : "l"(p));
    return a;
}
__device__ __forceinline__ void cp16(uint32_t sdst, const void* gsrc) {
    asm volatile("cp.async.cg.shared.global [%0], [%1], 16;" :: "r"(sdst), "l"(gsrc) : "memory");
}
#define CP_COMMIT() asm volatile("cp.async.commit_group;" ::: "memory")
#define CP_WAIT2()  asm volatile("cp.async.wait_group 2;" ::: "memory")

__device__ __forceinline__ void mma16816(float* d, uint32_t a0, uint32_t a1, uint32_t a2, uint32_t a3,
                                         uint32_t b0, uint32_t b1) {
    asm volatile("mma.sync.aligned.m16n8k16.row.col.f32.bf16.bf16.f32 "
        "{%0,%1,%2,%3}, {%4,%5,%6,%7}, {%8,%9}, {%0,%1,%2,%3};"
        : "+f"(d[0]), "+f"(d[1]), "+f"(d[2]), "+f"(d[3])
        : "r"(a0), "r"(a1), "r"(a2), "r"(a3), "r"(b0), "r"(b1));
}
#define LDSM4(r0, r1, r2, r3, addr) \
    asm volatile("ldmatrix.sync.aligned.m8n8.x4.shared.b16 {%0,%1,%2,%3}, [%4];" \
        : "=r"(r0), "=r"(r1), "=r"(r2), "=r"(r3) : "r"(addr))

// ---------------- init ----------------
__global__ void init_kernel(float* out, int out_size) {
    int i = blockIdx.x * blockDim.x + threadIdx.x;
    if (i < out_size) out[i] = 0.0f;
    if (i < BATCH) g_count[i] = 0;
}

// ---------------- fp32 -> bf16 elementwise (vec4) ----------------
__global__ void convert_a_kernel(const float* __restrict__ in, __nv_bfloat16* __restrict__ out, size_t n4) {
    size_t i = (size_t)blockIdx.x * blockDim.x + threadIdx.x;
    if (i >= n4) return;
    float4 v = ((const float4*)in)[i];
    __nv_bfloat162 p0, p1;
    p0.x = __float2bfloat16(v.x); p0.y = __float2bfloat16(v.y);
    p1.x = __float2bfloat16(v.z); p1.y = __float2bfloat16(v.w);
    ((__nv_bfloat162*)out)[2 * i]     = p0;
    ((__nv_bfloat162*)out)[2 * i + 1] = p1;
}

// ---------------- transpose + convert: [K,N] f32 -> [Npad,K] bf16 ----------------
__global__ void transpose_conv_kernel(const float* __restrict__ in, __nv_bfloat16* __restrict__ out,
                                      int K, int N, int Npad) {
    __shared__ float t[32][33];
    int n0 = blockIdx.x * 32, k0 = blockIdx.y * 32;
    int tx = threadIdx.x, ty = threadIdx.y;
    #pragma unroll
    for (int r = ty; r < 32; r += 8) {
        int k = k0 + r, n = n0 + tx;
        t[r][tx] = (k < K && n < N) ? in[(size_t)k * N + n] : 0.0f;
    }
    __syncthreads();
    #pragma unroll
    for (int r = ty; r < 32; r += 8) {
        int n = n0 + r, k = k0 + tx;
        if (n < Npad && k < K) out[(size_t)n * K + k] = __float2bfloat16(t[tx][r]);
    }
}

// ---------------- HMMA bf16 GEMM: 128x128 tile, 64x32 warp tile, ldmatrix, 4-stage ----------------
// A [M,Ktot] bf16 row-major, Bt [gridDim.x*128, Ktot] bf16 row-major (pre-transposed).
// ONE __syncthreads per K-chunk: the top barrier (after CP_WAIT2) orders stage reuse —
// stage (c+3)&3 written in iteration c was last read in iteration c-1, and every warp
// has finished c-1 before passing the barrier of c.
// OM: 0 = bf16 out (Cb); 1 = fp32 out guarded to Nvalid (C); 2 = both (stride Ntot).
#define ROWB 80                        // smem bytes per row (64 data + 16 pad)
#define AST  (128 * ROWB)              // 10240 B
#define STG  (2 * AST)                 // 20480 B per stage
#define NSTAGE 4
template<int OM, bool RELU>
__global__ __launch_bounds__(256)
void gemm_hmma(const __nv_bfloat16* __restrict__ A, const __nv_bfloat16* __restrict__ Bt,
               const float* __restrict__ bias, float* __restrict__ C,
               __nv_bfloat16* __restrict__ Cb, int Ktot, int Ntot, int Nvalid)
{
    extern __shared__ char smem[];
    const uint32_t sb = smem_u32(smem);
    const int tid = threadIdx.x, wid = tid >> 5, lane = tid & 31;
    const int g = lane >> 2, t4 = lane & 3;
    const int m0 = blockIdx.y * 128, n0 = blockIdx.x * 128;
    const int NCH = Ktot >> 5;          // K chunks of 32
    const int mw = (wid & 1) * 64;      // warp M origin
    const int nw = (wid >> 1) * 32;     // warp N origin

    float acc[4][4][4];
    #pragma unroll
    for (int i = 0; i < 4; i++)
        #pragma unroll
        for (int j = 0; j < 4; j++)
            #pragma unroll
            for (int r = 0; r < 4; r++) acc[i][j][r] = 0.0f;

    const uint32_t a_off = (uint32_t)(mw + (lane & 15)) * ROWB + ((lane >> 4) * 8) * 2;
    const uint32_t b_off = (uint32_t)(nw + (lane & 15)) * ROWB + ((lane >> 4) * 8) * 2;

    const int lrow = tid >> 1;          // 0..127
    const int lpart = tid & 1;

    auto load_chunk = [&](int c, int s) {
        const char* ag = (const char*)(A + (size_t)(m0 + lrow) * Ktot + (c << 5) + lpart * 16);
        uint32_t ad = sb + s * STG + lrow * ROWB + lpart * 32;
        cp16(ad, ag); cp16(ad + 16, ag + 16);
        const char* bg = (const char*)(Bt + (size_t)(n0 + lrow) * Ktot + (c << 5) + lpart * 16);
        uint32_t bd = ad + AST;
        cp16(bd, bg); cp16(bd + 16, bg + 16);
    };

    #pragma unroll
    for (int c = 0; c < NSTAGE - 1; c++) { load_chunk(c, c); CP_COMMIT(); }

    for (int c = 0; c < NCH; c++) {
        int s = c & (NSTAGE - 1);
        CP_WAIT2();
        __syncthreads();                // single barrier per chunk (see comment above)
        if (c + NSTAGE - 1 < NCH) load_chunk(c + NSTAGE - 1, (c + NSTAGE - 1) & (NSTAGE - 1));
        CP_COMMIT();

        const uint32_t sa = sb + s * STG;
        const uint32_t sbB = sa + AST;
        #pragma unroll
        for (int kk = 0; kk < 32; kk += 16) {
            uint32_t af[4][4], bf[4][2];
            #pragma unroll
            for (int i = 0; i < 4; i++)
                LDSM4(af[i][0], af[i][1], af[i][2], af[i][3],
                      sa + a_off + (uint32_t)(i * 16 * ROWB) + kk * 2);
            #pragma unroll
            for (int jp = 0; jp < 2; jp++)
                LDSM4(bf[2 * jp][0], bf[2 * jp + 1][0], bf[2 * jp][1], bf[2 * jp + 1][1],
                      sbB + b_off + (uint32_t)(jp * 16 * ROWB) + kk * 2);
            #pragma unroll
            for (int i = 0; i < 4; i++)
                #pragma unroll
                for (int j = 0; j < 4; j++)
                    mma16816(acc[i][j], af[i][0], af[i][1], af[i][2], af[i][3], bf[j][0], bf[j][1]);
        }
    }

    // epilogue
    #pragma unroll
    for (int i = 0; i < 4; i++) {
        #pragma unroll
        for (int j = 0; j < 4; j++) {
            int col = n0 + nw + j * 8 + 2 * t4;
            float b0, b1;
            if (OM == 1) { b0 = (col < Nvalid) ? bias[col] : 0.0f;
                           b1 = (col + 1 < Nvalid) ? bias[col + 1] : 0.0f; }
            else         { b0 = bias[col]; b1 = bias[col + 1]; }
            #pragma unroll
            for (int h = 0; h < 2; h++) {
                int row = m0 + mw + i * 16 + g + h * 8;
                float v0 = acc[i][j][2 * h]     + b0;
                float v1 = acc[i][j][2 * h + 1] + b1;
                if (RELU) { v0 = fmaxf(v0, 0.0f); v1 = fmaxf(v1, 0.0f); }
                if (OM == 0 || OM == 2) {
                    __nv_bfloat162 p; p.x = __float2bfloat16(v0); p.y = __float2bfloat16(v1);
                    *(__nv_bfloat162*)(Cb + (size_t)row * Ntot + col) = p;
                }
                if (OM == 1) {
                    if (col < Nvalid)     C[(size_t)row * Nvalid + col]     = v0;
                    if (col + 1 < Nvalid) C[(size_t)row * Nvalid + col + 1] = v1;
                }
                if (OM == 2) {
                    *(float2*)(C + (size_t)row * Ntot + col) = make_float2(v0, v1);
                }
            }
        }
    }
}

// ---------------- softmax + threshold + on-demand bbox decode ----------------
__global__ void softmax_cand_kernel(const float* __restrict__ bbox_w,
                                    const float* __restrict__ bbox_b,
                                    const float* __restrict__ proposals)
{
    int warp = (blockIdx.x * blockDim.x + threadIdx.x) >> 5;
    int lane = threadIdx.x & 31;
    if (warp >= NROWS) return;
    int n = warp;
    int img = n >> 11;

    const float* lrow = g_logits + (size_t)n * NCLS;
    float l0 = (lane      < NCLS) ? lrow[lane]      : -INFINITY;
    float l1 = (lane + 32 < NCLS) ? lrow[lane + 32] : -INFINITY;
    float l2 = (lane + 64 < NCLS) ? lrow[lane + 64] : -INFINITY;

    float mx = fmaxf(l0, fmaxf(l1, l2));
    #pragma unroll
    for (int o = 16; o; o >>= 1) mx = fmaxf(mx, __shfl_xor_sync(0xffffffffu, mx, o));

    float e0 = (lane      < NCLS) ? __expf(l0 - mx) : 0.0f;
    float e1 = (lane + 32 < NCLS) ? __expf(l1 - mx) : 0.0f;
    float e2 = (lane + 64 < NCLS) ? __expf(l2 - mx) : 0.0f;
    float s = e0 + e1 + e2;
    #pragma unroll
    for (int o = 16; o; o >>= 1) s += __shfl_xor_sync(0xffffffffu, s, o);
    float inv = 1.0f / s;

    #pragma unroll
    for (int base = 0; base < 96; base += 32) {
        int c = base + lane;
        float sc = (base == 0 ? e0 : (base == 32 ? e1 : e2)) * inv;
        bool cand = (c >= 1 && c < NCLS && sc > SCORE_THRESH);
        unsigned mask = __ballot_sync(0xffffffffu, cand);
        while (mask) {
            int src = __ffs(mask) - 1;
            mask &= mask - 1;
            int   cs  = base + src;
            float scs = __shfl_sync(0xffffffffu, sc, src);

            float rel[4];
            #pragma unroll
            for (int j = 0; j < 4; j++) {
                float acc = 0.0f;
                const float* h2row = g_h2 + (size_t)n * HID;
                for (int k = lane; k < HID; k += 32)
                    acc = fmaf(h2row[k], bbox_w[(size_t)k * REGC + 4 * cs + j], acc);
                #pragma unroll
                for (int o = 16; o; o >>= 1) acc += __shfl_xor_sync(0xffffffffu, acc, o);
                rel[j] = acc + bbox_b[4 * cs + j];
            }

            if (lane == 0) {
                float px1 = proposals[(size_t)n * 4 + 0];
                float py1 = proposals[(size_t)n * 4 + 1];
                float px2 = proposals[(size_t)n * 4 + 2];
                float py2 = proposals[(size_t)n * 4 + 3];
                float w  = px2 - px1, h = py2 - py1;
                float cx = px1 + 0.5f * w, cy = py1 + 0.5f * h;
                float dx = rel[0] * 0.1f, dy = rel[1] * 0.1f;
                float dw = fminf(rel[2] * 0.2f, BBOX_CLIP);
                float dh = fminf(rel[3] * 0.2f, BBOX_CLIP);
                float pcx = dx * w + cx, pcy = dy * h + cy;
                float pw = expf(dw) * w, ph = expf(dh) * h;
                float x1 = pcx - 0.5f * pw, y1 = pcy - 0.5f * ph;
                float x2 = pcx + 0.5f * pw, y2 = pcy + 0.5f * ph;
                x1 = fminf(fmaxf(x1, 0.0f), IMG_DIM);
                x2 = fminf(fmaxf(x2, 0.0f), IMG_DIM);
                y1 = fminf(fmaxf(y1, 0.0f), IMG_DIM);
                y2 = fminf(fmaxf(y2, 0.0f), IMG_DIM);
                float bw = x2 - x1, bh = y2 - y1;
                if (bw >= MIN_SIZE && bh >= MIN_SIZE) {
                    int idx = atomicAdd(&g_count[img], 1);
                    float off = (float)cs * CLS_OFFSET;
                    g_cbox[img][idx][0] = x1; g_cbox[img][idx][1] = y1;
                    g_cbox[img][idx][2] = x2; g_cbox[img][idx][3] = y2;
                    float ox1 = x1 + off, oy1 = y1 + off, ox2 = x2 + off, oy2 = y2 + off;
                    g_cob[img][idx][0] = ox1; g_cob[img][idx][1] = oy1;
                    g_cob[img][idx][2] = ox2; g_cob[img][idx][3] = oy2;
                    g_carea[img][idx]  = (ox2 - ox1) * (oy2 - oy1);
                    g_cscore[img][idx] = scs;
                    g_clabel[img][idx] = cs;
                }
            }
        }
    }
}

// ---------------- greedy batched NMS ----------------
__global__ void nms_kernel(float* __restrict__ out)
{
    __shared__ float s_val[256];
    __shared__ int   s_idx[256];
    __shared__ float s_bb[4];
    __shared__ float s_barea;

    int img = blockIdx.x;
    int tid = threadIdx.x;
    int cnt = g_count[img];

    for (int d = 0; d < DETS; d++) {
        float bv = -INFINITY;
        int   bi = -1;
        for (int i = tid; i < cnt; i += 256) {
            float v = g_cscore[img][i];
            if (v > bv || (v == bv && i < bi)) { bv = v; bi = i; }
        }
        s_val[tid] = bv; s_idx[tid] = bi;
        __syncthreads();
        for (int o = 128; o; o >>= 1) {
            if (tid < o) {
                float v2 = s_val[tid + o]; int i2 = s_idx[tid + o];
                float v1 = s_val[tid];     int i1 = s_idx[tid];
                if (v2 > v1 || (v2 == v1 && i2 != -1 && (i1 == -1 || i2 < i1))) {
                    s_val[tid] = v2; s_idx[tid] = i2;
                }
            }
            __syncthreads();
        }
        float bestv = s_val[0];
        int   besti = s_idx[0];
        if (besti < 0 || !isfinite(bestv)) break;

        if (tid == 0) {
            out[((size_t)img * DETS + d) * 4 + 0] = g_cbox[img][besti][0];
            out[((size_t)img * DETS + d) * 4 + 1] = g_cbox[img][besti][1];
            out[((size_t)img * DETS + d) * 4 + 2] = g_cbox[img][besti][2];
            out[((size_t)img * DETS + d) * 4 + 3] = g_cbox[img][besti][3];
            out[BATCH * DETS * 4 + img * DETS + d] = bestv;
            ((int*)out)[BATCH * DETS * 5 + img * DETS + d] = g_clabel[img][besti];
            s_bb[0] = g_cob[img][besti][0];
            s_bb[1] = g_cob[img][besti][1];
            s_bb[2] = g_cob[img][besti][2];
            s_bb[3] = g_cob[img][besti][3];
            s_barea = g_carea[img][besti];
        }
        __syncthreads();

        float bx1 = s_bb[0], by1 = s_bb[1], bx2 = s_bb[2], by2 = s_bb[3];
        float barea = s_barea;
        for (int i = tid; i < cnt; i += 256) {
            float x1 = fmaxf(g_cob[img][i][0], bx1);
            float y1 = fmaxf(g_cob[img][i][1], by1);
            float x2 = fminf(g_cob[img][i][2], bx2);
            float y2 = fminf(g_cob[img][i][3], by2);
            float inter = fmaxf(x2 - x1, 0.0f) * fmaxf(y2 - y1, 0.0f);
            float uni = fmaxf(g_carea[img][i] + barea - inter, 1e-6f);
            if (inter / uni > NMS_THRESH) g_cscore[img][i] = -INFINITY;
        }
        __syncthreads();
    }
}

// ---------------- launch ----------------
extern "C" void kernel_launch(void* const* d_in, const int* in_sizes, int n_in,
                              void* d_out, int out_size)
{
    const float* box_features = (const float*)d_in[0];
    const float* proposals    = (const float*)d_in[1];
    const float* fc6_w = (const float*)d_in[2];
    const float* fc6_b = (const float*)d_in[3];
    const float* fc7_w = (const float*)d_in[4];
    const float* fc7_b = (const float*)d_in[5];
    const float* cls_w = (const float*)d_in[6];
    const float* cls_b = (const float*)d_in[7];
    const float* bbox_w = (const float*)d_in[8];
    const float* bbox_b = (const float*)d_in[9];
    float* out = (float*)d_out;

    __nv_bfloat16 *p_a1, *p_w6t, *p_w7t, *p_wct, *p_h1b, *p_h2b;
    float *p_h2, *p_logits;
    cudaGetSymbolAddress((void**)&p_a1,  g_a1);
    cudaGetSymbolAddress((void**)&p_w6t, g_w6t);
    cudaGetSymbolAddress((void**)&p_w7t, g_w7t);
    cudaGetSymbolAddress((void**)&p_wct, g_wct);
    cudaGetSymbolAddress((void**)&p_h1b, g_h1b);
    cudaGetSymbolAddress((void**)&p_h2b, g_h2b);
    cudaGetSymbolAddress((void**)&p_h2,  g_h2);
    cudaGetSymbolAddress((void**)&p_logits, g_logits);

    const int SMEM = NSTAGE * STG;   // 81920 bytes
    cudaFuncSetAttribute(gemm_hmma<0, true>,  cudaFuncAttributeMaxDynamicSharedMemorySize, SMEM);
    cudaFuncSetAttribute(gemm_hmma<2, true>,  cudaFuncAttributeMaxDynamicSharedMemorySize, SMEM);
    cudaFuncSetAttribute(gemm_hmma<1, false>, cudaFuncAttributeMaxDynamicSharedMemorySize, SMEM);

    init_kernel<<<(out_size + 255) / 256, 256>>>(out, out_size);

    // convert box_features fp32 -> bf16
    size_t n4 = (size_t)NROWS * F_IN / 4;
    convert_a_kernel<<<(unsigned)((n4 + 255) / 256), 256>>>(box_features, p_a1, n4);

    // transpose+convert weights: [K,N] f32 -> [Npad,K] bf16
    transpose_conv_kernel<<<dim3((HID + 31) / 32, (F_IN + 31) / 32), dim3(32, 8)>>>(fc6_w, p_w6t, F_IN, HID, HID);
    transpose_conv_kernel<<<dim3((HID + 31) / 32, (HID + 31) / 32), dim3(32, 8)>>>(fc7_w, p_w7t, HID, HID, HID);
    transpose_conv_kernel<<<dim3((NCLSP + 31) / 32, (HID + 31) / 32), dim3(32, 8)>>>(cls_w, p_wct, HID, NCLS, NCLSP);

    // GEMM1: h1 = relu(A @ W6 + b6) -> bf16
    gemm_hmma<0, true><<<dim3(HID / 128, NROWS / 128), 256, SMEM>>>(
        p_a1, p_w6t, fc6_b, nullptr, p_h1b, F_IN, HID, HID);

    // GEMM2: h2 = relu(h1 @ W7 + b7) -> fp32 + bf16
    gemm_hmma<2, true><<<dim3(HID / 128, NROWS / 128), 256, SMEM>>>(
        p_h1b, p_w7t, fc7_b, p_h2, p_h2b, HID, HID, HID);

    // GEMM3: logits = h2 @ Wc + bc -> fp32 [8192, 91]
    gemm_hmma<1, false><<<dim3(1, NROWS / 128), 256, SMEM>>>(
        p_h2b, p_wct, cls_b, p_logits, nullptr, HID, NCLSP, NCLS);

    softmax_cand_kernel<<<NROWS / 8, 256>>>(bbox_w, bbox_b, proposals);
    nms_kernel<<<BATCH, 256>>>(out);
}